// round 1
// baseline (speedup 1.0000x reference)
#include <cuda_runtime.h>
#include <cuda_fp16.h>
#include <cuda_bf16.h>
#include <stdint.h>

// ---------------------------------------------------------------------------
// Problem constants: B=2, S=2048, H=2048, NH=16, HD=128, W=512
//   rows M = B*S = 4096, hidden N=K=2048
// ---------------------------------------------------------------------------
#define MROWS 4096
#define HID   2048
#define SEQ   2048
#define NHEAD 16
#define HDIM  128
#define WIN   512

// ------------------------- device scratch (no runtime alloc allowed) -------
__device__ __half g_y [MROWS * HID];
__device__ __half g_q [MROWS * HID];
__device__ __half g_k [MROWS * HID];
__device__ __half g_v [MROWS * HID];
__device__ __half g_o [MROWS * HID];
__device__ __half g_wq[HID * HID];
__device__ __half g_wk[HID * HID];
__device__ __half g_wv[HID * HID];
__device__ __half g_wo[HID * HID];

// ------------------------- PTX helpers -------------------------------------
__device__ __forceinline__ uint32_t smem_u32(const void* p) {
    return (uint32_t)__cvta_generic_to_shared(p);
}
__device__ __forceinline__ void ldsm4(uint32_t (&r)[4], uint32_t a) {
    asm volatile("ldmatrix.sync.aligned.m8n8.x4.shared.b16 {%0,%1,%2,%3}, [%4];"
                 : "=r"(r[0]), "=r"(r[1]), "=r"(r[2]), "=r"(r[3]) : "r"(a));
}
__device__ __forceinline__ void ldsm4t(uint32_t (&r)[4], uint32_t a) {
    asm volatile("ldmatrix.sync.aligned.m8n8.x4.trans.shared.b16 {%0,%1,%2,%3}, [%4];"
                 : "=r"(r[0]), "=r"(r[1]), "=r"(r[2]), "=r"(r[3]) : "r"(a));
}
__device__ __forceinline__ void mma16816(float (&c)[4], const uint32_t (&a)[4],
                                         uint32_t b0, uint32_t b1) {
    asm volatile("mma.sync.aligned.m16n8k16.row.col.f32.f16.f16.f32 "
                 "{%0,%1,%2,%3}, {%4,%5,%6,%7}, {%8,%9}, {%0,%1,%2,%3};"
                 : "+f"(c[0]), "+f"(c[1]), "+f"(c[2]), "+f"(c[3])
                 : "r"(a[0]), "r"(a[1]), "r"(a[2]), "r"(a[3]), "r"(b0), "r"(b1));
}
__device__ __forceinline__ void cpasync16(uint32_t s, const void* g) {
    asm volatile("cp.async.cg.shared.global [%0], [%1], 16;" :: "r"(s), "l"(g));
}
#define CP_COMMIT() asm volatile("cp.async.commit_group;")
#define CP_WAIT0()  asm volatile("cp.async.wait_group 0;")
#define CP_WAIT1()  asm volatile("cp.async.wait_group 1;")

__device__ __forceinline__ uint32_t packh2(float lo, float hi) {
    __half2 h = __floats2half2_rn(lo, hi);
    return *reinterpret_cast<uint32_t*>(&h);
}

// ------------------------- fp32 -> fp16 convert -----------------------------
__global__ __launch_bounds__(256) void f2h_kernel(const float* __restrict__ src,
                                                  __half* __restrict__ dst, int n4) {
    int i = blockIdx.x * blockDim.x + threadIdx.x;
    if (i >= n4) return;
    float4 v = reinterpret_cast<const float4*>(src)[i];
    __half2* d = reinterpret_cast<__half2*>(dst) + i * 2;
    d[0] = __floats2half2_rn(v.x, v.y);
    d[1] = __floats2half2_rn(v.z, v.w);
}

// ------------------------- LayerNorm -> fp16 --------------------------------
__global__ __launch_bounds__(256) void ln_kernel(const float* __restrict__ x,
                                                 const float* __restrict__ sc,
                                                 const float* __restrict__ bi,
                                                 __half* __restrict__ y) {
    const int row = blockIdx.x;
    const int tid = threadIdx.x;
    const float4* xr = reinterpret_cast<const float4*>(x + (size_t)row * HID);
    float4 v[2];
    float sum = 0.f, sq = 0.f;
#pragma unroll
    for (int i = 0; i < 2; i++) {
        v[i] = xr[tid + i * 256];
        sum += v[i].x + v[i].y + v[i].z + v[i].w;
        sq  += v[i].x * v[i].x + v[i].y * v[i].y + v[i].z * v[i].z + v[i].w * v[i].w;
    }
#pragma unroll
    for (int o = 16; o > 0; o >>= 1) {
        sum += __shfl_xor_sync(0xffffffffu, sum, o);
        sq  += __shfl_xor_sync(0xffffffffu, sq,  o);
    }
    __shared__ float rs[8], rq[8];
    if ((tid & 31) == 0) { rs[tid >> 5] = sum; rq[tid >> 5] = sq; }
    __syncthreads();
    sum = 0.f; sq = 0.f;
#pragma unroll
    for (int i = 0; i < 8; i++) { sum += rs[i]; sq += rq[i]; }
    const float mu   = sum * (1.f / HID);
    const float var  = sq * (1.f / HID) - mu * mu;
    const float rstd = rsqrtf(var + 1e-6f);

    __half2* yr = reinterpret_cast<__half2*>(y + (size_t)row * HID);
#pragma unroll
    for (int i = 0; i < 2; i++) {
        int c = (tid + i * 256) * 4;
        float o0 = (v[i].x - mu) * rstd * sc[c + 0] + bi[c + 0];
        float o1 = (v[i].y - mu) * rstd * sc[c + 1] + bi[c + 1];
        float o2 = (v[i].z - mu) * rstd * sc[c + 2] + bi[c + 2];
        float o3 = (v[i].w - mu) * rstd * sc[c + 3] + bi[c + 3];
        yr[(c >> 1) + 0] = __floats2half2_rn(o0, o1);
        yr[(c >> 1) + 1] = __floats2half2_rn(o2, o3);
    }
}

// ------------------------- GEMM: C[M,N] = (A[M,K] * B[K,N] + bias) * alpha --
// A fp16 row-major, B fp16 row-major (k-major), bias per-column fp32.
// 128x128x32 tiles, 8 warps (2M x 4N), warp tile 64x32, cp.async 2-stage.
template <typename OutT>
__global__ __launch_bounds__(256, 1) void gemm_kernel(const __half* __restrict__ A,
                                                      const __half* __restrict__ Bm,
                                                      const float* __restrict__ bias,
                                                      OutT* __restrict__ C,
                                                      float alpha) {
    constexpr int N = HID, Kd = HID;
    __shared__ __half sA[2][128][40];
    __shared__ __half sB[2][32][136];
    const int tid = threadIdx.x, warp = tid >> 5, lane = tid & 31;
    const int wm = warp & 1, wn = warp >> 1;
    const int bm = blockIdx.y * 128, bn = blockIdx.x * 128;

    float acc[4][4][4];
#pragma unroll
    for (int a = 0; a < 4; a++)
#pragma unroll
        for (int b = 0; b < 4; b++)
#pragma unroll
            for (int c = 0; c < 4; c++) acc[a][b][c] = 0.f;

    auto ldA = [&](int st, int k0) {
#pragma unroll
        for (int v = tid; v < 512; v += 256) {
            int r = v >> 2, c = (v & 3) * 8;
            cpasync16(smem_u32(&sA[st][r][c]), A + (size_t)(bm + r) * Kd + k0 + c);
        }
    };
    auto ldB = [&](int st, int k0) {
#pragma unroll
        for (int v = tid; v < 512; v += 256) {
            int r = v >> 4, c = (v & 15) * 8;
            cpasync16(smem_u32(&sB[st][r][c]), Bm + (size_t)(k0 + r) * N + bn + c);
        }
    };

    ldA(0, 0); ldB(0, 0); CP_COMMIT();

    for (int kt = 0; kt < Kd / 32; kt++) {
        const int cur = kt & 1;
        CP_WAIT0();
        __syncthreads();
        if (kt + 1 < Kd / 32) { ldA(cur ^ 1, (kt + 1) * 32); ldB(cur ^ 1, (kt + 1) * 32); CP_COMMIT(); }
#pragma unroll
        for (int ks = 0; ks < 2; ks++) {
            uint32_t a[4][4];
#pragma unroll
            for (int mt = 0; mt < 4; mt++)
                ldsm4(a[mt], smem_u32(&sA[cur][wm * 64 + mt * 16 + (lane & 15)]
                                         [ks * 16 + (lane >> 4) * 8]));
            uint32_t bf[4][2];
#pragma unroll
            for (int np = 0; np < 2; np++) {
                uint32_t r[4];
                ldsm4t(r, smem_u32(&sB[cur][ks * 16 + (lane & 15)]
                                      [wn * 32 + np * 16 + (lane >> 4) * 8]));
                bf[2 * np][0] = r[0]; bf[2 * np][1] = r[1];
                bf[2 * np + 1][0] = r[2]; bf[2 * np + 1][1] = r[3];
            }
#pragma unroll
            for (int mt = 0; mt < 4; mt++)
#pragma unroll
                for (int nt = 0; nt < 4; nt++)
                    mma16816(acc[mt][nt], a[mt], bf[nt][0], bf[nt][1]);
        }
        __syncthreads();
    }

    const int g = lane >> 2, t4 = lane & 3;
#pragma unroll
    for (int mt = 0; mt < 4; mt++) {
#pragma unroll
        for (int nt = 0; nt < 4; nt++) {
            int row = bm + wm * 64 + mt * 16 + g;
            int col = bn + wn * 32 + nt * 8 + 2 * t4;
            float b0 = bias[col], b1 = bias[col + 1];
            float v0 = (acc[mt][nt][0] + b0) * alpha;
            float v1 = (acc[mt][nt][1] + b1) * alpha;
            float v2 = (acc[mt][nt][2] + b0) * alpha;
            float v3 = (acc[mt][nt][3] + b1) * alpha;
            if constexpr (sizeof(OutT) == 2) {
                *reinterpret_cast<__half2*>(&C[(size_t)row * N + col])       = __floats2half2_rn(v0, v1);
                *reinterpret_cast<__half2*>(&C[(size_t)(row + 8) * N + col]) = __floats2half2_rn(v2, v3);
            } else {
                *reinterpret_cast<float2*>(&C[(size_t)row * N + col])       = make_float2(v0, v1);
                *reinterpret_cast<float2*>(&C[(size_t)(row + 8) * N + col]) = make_float2(v2, v3);
            }
        }
    }
}

// ------------------------- attention (complement of sliding causal band) ----
// Attend iff j > i  OR  j <= i - WIN.  Per 128-q-tile: skip fully-masked key
// tiles k0 in {q0-128, q0-256, q0-384}; elementwise mask only k0==q0, k0==q0-512.
#define APITCH 136
#define ATT_SMEM (5 * 128 * APITCH * 2)   // Q + 2*K + 2*V tiles = 174080 B

__global__ __launch_bounds__(256, 1) void attn_kernel(const __half* __restrict__ Q,
                                                      const __half* __restrict__ K,
                                                      const __half* __restrict__ V,
                                                      __half* __restrict__ O) {
    extern __shared__ __half sm[];
    __half* sQ = sm;                       // [128][APITCH]
    __half* sK = sm + 128 * APITCH;        // [2][128][APITCH]
    __half* sV = sK + 2 * 128 * APITCH;    // [2][128][APITCH]

    const int tid = threadIdx.x, warp = tid >> 5, lane = tid & 31;
    const int bh = blockIdx.y, b = bh >> 4, h = bh & 15;
    const int q0 = blockIdx.x * 128;
    const size_t headoff = ((size_t)b * SEQ) * HID + (size_t)h * HDIM;

    // Q tile load
#pragma unroll
    for (int v = tid; v < 2048; v += 256) {
        int r = v >> 4, c = (v & 15) * 8;
        cpasync16(smem_u32(&sQ[r * APITCH + c]), Q + headoff + (size_t)(q0 + r) * HID + c);
    }
    CP_COMMIT();

    // valid key-tile list (skip fully-masked band tiles)
    int list[16], nv = 0;
#pragma unroll
    for (int tt = 0; tt < 16; tt++) {
        int k0 = tt << 7;
        bool skip = (k0 >= q0 - 384) && (k0 <= q0 - 128);
        if (!skip) list[nv++] = tt;
    }

    // prefetch first K/V tile
    {
        int k0 = list[0] << 7;
#pragma unroll
        for (int v = tid; v < 2048; v += 256) {
            int r = v >> 4, c = (v & 15) * 8;
            size_t go = headoff + (size_t)(k0 + r) * HID + c;
            cpasync16(smem_u32(&sK[r * APITCH + c]), K + go);
            cpasync16(smem_u32(&sV[r * APITCH + c]), V + go);
        }
        CP_COMMIT();
    }

    CP_WAIT1();          // Q ready (first KV group may still be in flight)
    __syncthreads();

    // Q fragments (16 rows per warp, full d=128)
    uint32_t qa[8][4];
    const int mbase = warp * 16;
#pragma unroll
    for (int kt = 0; kt < 8; kt++)
        ldsm4(qa[kt], smem_u32(&sQ[(mbase + (lane & 15)) * APITCH + kt * 16 + (lane >> 4) * 8]));

    float accO[16][4];
#pragma unroll
    for (int a = 0; a < 16; a++)
#pragma unroll
        for (int c = 0; c < 4; c++) accO[a][c] = 0.f;

    const int g = lane >> 2, t4 = lane & 3;
    const int qi0 = q0 + mbase + g, qi1 = qi0 + 8;
    float m0 = -1e30f, m1 = -1e30f, l0 = 0.f, l1 = 0.f;

    for (int ii = 0; ii < nv; ii++) {
        const int tt = list[ii], k0 = tt << 7, cur = ii & 1;
        CP_WAIT0();
        __syncthreads();
        if (ii + 1 < nv) {
            int kn = list[ii + 1] << 7, nb = cur ^ 1;
#pragma unroll
            for (int v = tid; v < 2048; v += 256) {
                int r = v >> 4, c = (v & 15) * 8;
                size_t go = headoff + (size_t)(kn + r) * HID + c;
                cpasync16(smem_u32(&sK[(nb * 128 + r) * APITCH + c]), K + go);
                cpasync16(smem_u32(&sV[(nb * 128 + r) * APITCH + c]), V + go);
            }
            CP_COMMIT();
        }
        const __half* sKc = sK + cur * 128 * APITCH;
        const __half* sVc = sV + cur * 128 * APITCH;

        // S = Q * K^T
        float s[16][4];
#pragma unroll
        for (int a = 0; a < 16; a++)
#pragma unroll
            for (int c = 0; c < 4; c++) s[a][c] = 0.f;
#pragma unroll
        for (int kt = 0; kt < 8; kt++) {
#pragma unroll
            for (int np = 0; np < 8; np++) {
                uint32_t r[4];
                ldsm4(r, smem_u32(&sKc[(np * 16 + (lane & 15)) * APITCH + kt * 16 + (lane >> 4) * 8]));
                mma16816(s[2 * np],     qa[kt], r[0], r[2]);
                mma16816(s[2 * np + 1], qa[kt], r[1], r[3]);
            }
        }

        // inverted-band mask (keep j>i or j<=i-WIN)
        if (k0 == q0) {
#pragma unroll
            for (int nt = 0; nt < 16; nt++) {
                int j = k0 + nt * 8 + 2 * t4;
                if (j     <= qi0) s[nt][0] = -1e30f;
                if (j + 1 <= qi0) s[nt][1] = -1e30f;
                if (j     <= qi1) s[nt][2] = -1e30f;
                if (j + 1 <= qi1) s[nt][3] = -1e30f;
            }
        } else if (k0 == q0 - WIN) {
#pragma unroll
            for (int nt = 0; nt < 16; nt++) {
                int j = k0 + nt * 8 + 2 * t4;
                if (j     > qi0 - WIN) s[nt][0] = -1e30f;
                if (j + 1 > qi0 - WIN) s[nt][1] = -1e30f;
                if (j     > qi1 - WIN) s[nt][2] = -1e30f;
                if (j + 1 > qi1 - WIN) s[nt][3] = -1e30f;
            }
        }

        // online softmax (rows owned by a lane quad)
        float rm0 = -1e30f, rm1 = -1e30f;
#pragma unroll
        for (int nt = 0; nt < 16; nt++) {
            rm0 = fmaxf(rm0, fmaxf(s[nt][0], s[nt][1]));
            rm1 = fmaxf(rm1, fmaxf(s[nt][2], s[nt][3]));
        }
        rm0 = fmaxf(rm0, __shfl_xor_sync(0xffffffffu, rm0, 1));
        rm0 = fmaxf(rm0, __shfl_xor_sync(0xffffffffu, rm0, 2));
        rm1 = fmaxf(rm1, __shfl_xor_sync(0xffffffffu, rm1, 1));
        rm1 = fmaxf(rm1, __shfl_xor_sync(0xffffffffu, rm1, 2));

        float nm0 = fmaxf(m0, rm0), nm1 = fmaxf(m1, rm1);
        float nm0s = (nm0 < -1e29f) ? 0.f : nm0;
        float nm1s = (nm1 < -1e29f) ? 0.f : nm1;
        float al0 = __expf(m0 - nm0s), al1 = __expf(m1 - nm1s);
        float rs0 = 0.f, rs1 = 0.f;
#pragma unroll
        for (int nt = 0; nt < 16; nt++) {
            s[nt][0] = __expf(s[nt][0] - nm0s);
            s[nt][1] = __expf(s[nt][1] - nm0s);
            s[nt][2] = __expf(s[nt][2] - nm1s);
            s[nt][3] = __expf(s[nt][3] - nm1s);
            rs0 += s[nt][0] + s[nt][1];
            rs1 += s[nt][2] + s[nt][3];
        }
        rs0 += __shfl_xor_sync(0xffffffffu, rs0, 1);
        rs0 += __shfl_xor_sync(0xffffffffu, rs0, 2);
        rs1 += __shfl_xor_sync(0xffffffffu, rs1, 1);
        rs1 += __shfl_xor_sync(0xffffffffu, rs1, 2);
        l0 = l0 * al0 + rs0;
        l1 = l1 * al1 + rs1;
        m0 = nm0; m1 = nm1;
#pragma unroll
        for (int nt = 0; nt < 16; nt++) {
            accO[nt][0] *= al0; accO[nt][1] *= al0;
            accO[nt][2] *= al1; accO[nt][3] *= al1;
        }

        // accO += P * V   (P stays in registers as fp16 A-fragments)
#pragma unroll
        for (int kt = 0; kt < 8; kt++) {
            uint32_t pa[4];
            pa[0] = packh2(s[2 * kt][0],     s[2 * kt][1]);
            pa[1] = packh2(s[2 * kt][2],     s[2 * kt][3]);
            pa[2] = packh2(s[2 * kt + 1][0], s[2 * kt + 1][1]);
            pa[3] = packh2(s[2 * kt + 1][2], s[2 * kt + 1][3]);
#pragma unroll
            for (int dp = 0; dp < 8; dp++) {
                uint32_t r[4];
                ldsm4t(r, smem_u32(&sVc[(kt * 16 + (lane & 15)) * APITCH + dp * 16 + (lane >> 4) * 8]));
                mma16816(accO[2 * dp],     pa, r[0], r[1]);
                mma16816(accO[2 * dp + 1], pa, r[2], r[3]);
            }
        }
    }

    const float inv0 = 1.f / l0, inv1 = 1.f / l1;
    __half* o0 = O + headoff + (size_t)qi0 * HID;
    __half* o1 = O + headoff + (size_t)qi1 * HID;
#pragma unroll
    for (int nt = 0; nt < 16; nt++) {
        int d = nt * 8 + 2 * t4;
        *reinterpret_cast<__half2*>(o0 + d) = __floats2half2_rn(accO[nt][0] * inv0, accO[nt][1] * inv0);
        *reinterpret_cast<__half2*>(o1 + d) = __floats2half2_rn(accO[nt][2] * inv1, accO[nt][3] * inv1);
    }
}

// ------------------------- launcher ----------------------------------------
extern "C" void kernel_launch(void* const* d_in, const int* in_sizes, int n_in,
                              void* d_out, int out_size) {
    (void)in_sizes; (void)n_in; (void)out_size;
    const float* x    = (const float*)d_in[0];
    const float* ln_s = (const float*)d_in[1];
    const float* ln_b = (const float*)d_in[2];
    const float* wq   = (const float*)d_in[3];
    const float* bq   = (const float*)d_in[4];
    const float* wk   = (const float*)d_in[5];
    const float* bk   = (const float*)d_in[6];
    const float* wv   = (const float*)d_in[7];
    const float* bv   = (const float*)d_in[8];
    const float* wo   = (const float*)d_in[9];
    const float* bo   = (const float*)d_in[10];
    float* out = (float*)d_out;

    __half *yh, *qh, *kh, *vh, *oh, *wqh, *wkh, *wvh, *woh;
    cudaGetSymbolAddress((void**)&yh,  g_y);
    cudaGetSymbolAddress((void**)&qh,  g_q);
    cudaGetSymbolAddress((void**)&kh,  g_k);
    cudaGetSymbolAddress((void**)&vh,  g_v);
    cudaGetSymbolAddress((void**)&oh,  g_o);
    cudaGetSymbolAddress((void**)&wqh, g_wq);
    cudaGetSymbolAddress((void**)&wkh, g_wk);
    cudaGetSymbolAddress((void**)&wvh, g_wv);
    cudaGetSymbolAddress((void**)&woh, g_wo);

    cudaFuncSetAttribute(attn_kernel, cudaFuncAttributeMaxDynamicSharedMemorySize, ATT_SMEM);

    const int wElems = HID * HID;            // 4194304
    const int wVec4  = wElems / 4;           // 1048576
    f2h_kernel<<<wVec4 / 256, 256>>>(wq, wqh, wVec4);
    f2h_kernel<<<wVec4 / 256, 256>>>(wk, wkh, wVec4);
    f2h_kernel<<<wVec4 / 256, 256>>>(wv, wvh, wVec4);
    f2h_kernel<<<wVec4 / 256, 256>>>(wo, woh, wVec4);

    ln_kernel<<<MROWS, 256>>>(x, ln_s, ln_b, yh);

    dim3 gg(HID / 128, MROWS / 128);         // (16, 32)
    const float qscale = 0.08838834764831845f;   // 1/sqrt(128)
    gemm_kernel<__half><<<gg, 256>>>(yh, wqh, bq, qh, qscale);
    gemm_kernel<__half><<<gg, 256>>>(yh, wkh, bk, kh, 1.f);
    gemm_kernel<__half><<<gg, 256>>>(yh, wvh, bv, vh, 1.f);

    attn_kernel<<<dim3(SEQ / 128, 2 * NHEAD), 256, ATT_SMEM>>>(qh, kh, vh, oh);

    gemm_kernel<float><<<gg, 256>>>(oh, woh, bo, out, 1.f);
}

// round 5
// speedup vs baseline: 1.2584x; 1.2584x over previous
#include <cuda_runtime.h>
#include <cuda_fp16.h>
#include <stdint.h>

#define MROWS 4096
#define HID   2048
#define SEQ   2048
#define NHEAD 16
#define HDIM  128
#define WIN   512

// ---- device scratch --------------------------------------------------------
__device__ __align__(1024) __half g_yswz[MROWS * HID];   // LN out, blocked-SW128 A layout
__device__ __align__(1024) __half g_oswz[MROWS * HID];   // attn out, blocked-SW128 A layout
__device__ __align__(1024) __half g_wqT[HID * HID];      // W^T, blocked-SW128 B layout
__device__ __align__(1024) __half g_wkT[HID * HID];
__device__ __align__(1024) __half g_wvT[HID * HID];
__device__ __align__(1024) __half g_woT[HID * HID];
__device__ __align__(256)  __half g_q[MROWS * HID];      // row-major
__device__ __align__(256)  __half g_k[MROWS * HID];
__device__ __align__(256)  __half g_v[MROWS * HID];

// ---- PTX helpers -----------------------------------------------------------
__device__ __forceinline__ uint32_t smem_u32(const void* p) {
    return (uint32_t)__cvta_generic_to_shared(p);
}
__device__ __forceinline__ uint32_t swz128(uint32_t o) { return o ^ ((o >> 3) & 0x70); }
__device__ __forceinline__ void ldsm4(uint32_t (&r)[4], uint32_t a) {
    asm volatile("ldmatrix.sync.aligned.m8n8.x4.shared.b16 {%0,%1,%2,%3}, [%4];"
                 : "=r"(r[0]), "=r"(r[1]), "=r"(r[2]), "=r"(r[3]) : "r"(a));
}
__device__ __forceinline__ void ldsm4t(uint32_t (&r)[4], uint32_t a) {
    asm volatile("ldmatrix.sync.aligned.m8n8.x4.trans.shared.b16 {%0,%1,%2,%3}, [%4];"
                 : "=r"(r[0]), "=r"(r[1]), "=r"(r[2]), "=r"(r[3]) : "r"(a));
}
__device__ __forceinline__ void mma16816(float (&c)[4], const uint32_t (&a)[4],
                                         uint32_t b0, uint32_t b1) {
    asm volatile("mma.sync.aligned.m16n8k16.row.col.f32.f16.f16.f32 "
                 "{%0,%1,%2,%3}, {%4,%5,%6,%7}, {%8,%9}, {%0,%1,%2,%3};"
                 : "+f"(c[0]), "+f"(c[1]), "+f"(c[2]), "+f"(c[3])
                 : "r"(a[0]), "r"(a[1]), "r"(a[2]), "r"(a[3]), "r"(b0), "r"(b1));
}
__device__ __forceinline__ void cpasync16(uint32_t s, const void* g) {
    asm volatile("cp.async.cg.shared.global [%0], [%1], 16;" :: "r"(s), "l"(g));
}
#define CP_COMMIT() asm volatile("cp.async.commit_group;")
#define CP_WAIT0()  asm volatile("cp.async.wait_group 0;")
#define CP_WAIT1()  asm volatile("cp.async.wait_group 1;")
__device__ __forceinline__ uint32_t packh2(float lo, float hi) {
    __half2 h = __floats2half2_rn(lo, hi);
    return *reinterpret_cast<uint32_t*>(&h);
}
__device__ __forceinline__ void mbar_init(uint32_t a, uint32_t cnt) {
    asm volatile("mbarrier.init.shared.b64 [%0], %1;" :: "r"(a), "r"(cnt) : "memory");
}
__device__ __forceinline__ void mbar_expect(uint32_t a, uint32_t bytes) {
    asm volatile("mbarrier.arrive.expect_tx.shared.b64 _, [%0], %1;"
                 :: "r"(a), "r"(bytes) : "memory");
}
__device__ __forceinline__ void mbar_arrive(uint32_t a) {
    asm volatile("mbarrier.arrive.shared.b64 _, [%0];" :: "r"(a) : "memory");
}
__device__ __forceinline__ void mbar_wait(uint32_t a, uint32_t parity) {
    asm volatile(
        "{\n\t.reg .pred P;\n"
        "W_%=:\n\t"
        "mbarrier.try_wait.parity.acquire.cta.shared::cta.b64 P, [%0], %1, 0x989680;\n\t"
        "@!P bra W_%=;\n\t}"
        :: "r"(a), "r"(parity) : "memory");
}
__device__ __forceinline__ void bulk_g2s(uint32_t dst, const void* src,
                                         uint32_t bytes, uint32_t mbar) {
    asm volatile("cp.async.bulk.shared::cluster.global.mbarrier::complete_tx::bytes "
                 "[%0], [%1], %2, [%3];"
                 :: "r"(dst), "l"(src), "r"(bytes), "r"(mbar) : "memory");
}

// ---- weight transpose: fp32 [K,N] row-major -> half blocked-SW128 B layout -
// B layout: block idx = (n>>8)*32 + (k>>6); block = 256 n-rows x 128B (SW128)
__global__ __launch_bounds__(256) void wtx_kernel(const float* __restrict__ src,
                                                  __half* __restrict__ dst) {
    __shared__ float t[64][65];
    const int tid = threadIdx.x;
    const int n0 = blockIdx.x * 64, k0 = blockIdx.y * 64;
    const int rr = tid >> 6, cc = tid & 63;
#pragma unroll
    for (int j = 0; j < 16; j++) {
        int r = j * 4 + rr;
        t[r][cc] = src[(size_t)(k0 + r) * HID + n0 + cc];   // t[k_local][n_local]
    }
    __syncthreads();
    char* d = (char*)dst;
#pragma unroll
    for (int j = 0; j < 16; j++) {
        int n = n0 + j * 4 + rr, k = k0 + cc;
        uint32_t addr = (uint32_t)((n >> 8) * 32 + (k >> 6)) * 32768u
                      + swz128((uint32_t)(n & 255) * 128u + (uint32_t)(k & 63) * 2u);
        *reinterpret_cast<__half*>(d + addr) = __float2half(t[cc][j * 4 + rr]);
    }
}

// ---- LayerNorm -> half blocked-SW128 A layout ------------------------------
// A layout: block idx = (row>>7)*32 + (col>>6); block = 128 rows x 128B (SW128)
__global__ __launch_bounds__(256) void ln_kernel(const float* __restrict__ x,
                                                 const float* __restrict__ sc,
                                                 const float* __restrict__ bi,
                                                 __half* __restrict__ y) {
    const int row = blockIdx.x;
    const int tid = threadIdx.x;
    const float4* xr = reinterpret_cast<const float4*>(x + (size_t)row * HID);
    float4 v[2];
    float sum = 0.f, sq = 0.f;
#pragma unroll
    for (int i = 0; i < 2; i++) {
        v[i] = xr[tid + i * 256];
        sum += v[i].x + v[i].y + v[i].z + v[i].w;
        sq  += v[i].x * v[i].x + v[i].y * v[i].y + v[i].z * v[i].z + v[i].w * v[i].w;
    }
#pragma unroll
    for (int o = 16; o > 0; o >>= 1) {
        sum += __shfl_xor_sync(0xffffffffu, sum, o);
        sq  += __shfl_xor_sync(0xffffffffu, sq,  o);
    }
    __shared__ float rs[8], rq[8];
    if ((tid & 31) == 0) { rs[tid >> 5] = sum; rq[tid >> 5] = sq; }
    __syncthreads();
    sum = 0.f; sq = 0.f;
#pragma unroll
    for (int i = 0; i < 8; i++) { sum += rs[i]; sq += rq[i]; }
    const float mu   = sum * (1.f / HID);
    const float var  = sq * (1.f / HID) - mu * mu;
    const float rstd = rsqrtf(var + 1e-6f);

    char* yb = (char*)y;
    const uint32_t mblk = (uint32_t)(row >> 7) * 32u;
    const uint32_t rin  = (uint32_t)(row & 127) * 128u;
#pragma unroll
    for (int i = 0; i < 2; i++) {
        int c = (tid + i * 256) * 4;
        float o0 = (v[i].x - mu) * rstd * sc[c + 0] + bi[c + 0];
        float o1 = (v[i].y - mu) * rstd * sc[c + 1] + bi[c + 1];
        float o2 = (v[i].z - mu) * rstd * sc[c + 2] + bi[c + 2];
        float o3 = (v[i].w - mu) * rstd * sc[c + 3] + bi[c + 3];
        uint32_t base = (mblk + (uint32_t)(c >> 6)) * 16384u;
        uint32_t off  = swz128(rin + (uint32_t)(c & 63) * 2u);
        *reinterpret_cast<uint32_t*>(yb + base + off)     = packh2(o0, o1);
        *reinterpret_cast<uint32_t*>(yb + base + off + 4) = packh2(o2, o3);
    }
}

// ---- HMMA GEMM, bulk-copy pipeline -----------------------------------------
// C[4096,2048] = A(blocked-swz) @ B^T(blocked-swz) + bias, *alpha
// CTA tile 128x256, K-chunk 64, 3-stage ring, 8 warps (2m x 4n), warp 64x64.
#define GST      3
#define GA_BYTES 16384
#define GB_BYTES 32768
#define GSTAGE   (GA_BYTES + GB_BYTES)      // 49152
#define GEMM_DYN (GST * GSTAGE + 1024)      // 148480

struct GemmArgs {
    const char*  Bw[3];
    const float* bias[3];
    void*        C[3];
    float        alpha[3];
};

template <typename OutT>
__global__ __launch_bounds__(256, 1) void hgemm_kernel(const char* __restrict__ Ab,
                                                       GemmArgs ga) {
    extern __shared__ char dyn[];
    const uint32_t dyn0  = smem_u32(dyn);
    const uint32_t dbase = (dyn0 + 1023u) & ~1023u;

    __shared__ __align__(8) uint64_t mb_full[GST], mb_empty[GST];
    __shared__ float sBias[256];

    const int z = blockIdx.z;
    const int tid = threadIdx.x, warp = tid >> 5, lane = tid & 31;
    const int wm = warp & 1, wn = warp >> 1;
    const int bn = blockIdx.x * 256, bm = blockIdx.y * 128;

    sBias[tid] = ga.bias[z][bn + tid];
    uint32_t mf[GST], me[GST];
#pragma unroll
    for (int s = 0; s < GST; s++) { mf[s] = smem_u32(&mb_full[s]); me[s] = smem_u32(&mb_empty[s]); }
    if (tid == 0) {
#pragma unroll
        for (int s = 0; s < GST; s++) { mbar_init(mf[s], 1); mbar_init(me[s], 256); }
    }
    __syncthreads();

    const char* Asrc = Ab + (size_t)blockIdx.y * (32 * GA_BYTES);
    const char* Bsrc = ga.Bw[z] + (size_t)blockIdx.x * (32 * GB_BYTES);

    auto fill = [&](int kc) {
        int s = kc % GST;
        mbar_expect(mf[s], GSTAGE);
        bulk_g2s(dbase + s * GSTAGE,            Asrc + (size_t)kc * GA_BYTES, GA_BYTES, mf[s]);
        bulk_g2s(dbase + s * GSTAGE + GA_BYTES, Bsrc + (size_t)kc * GB_BYTES, GB_BYTES, mf[s]);
    };
    if (tid == 0) { fill(0); fill(1); fill(2); }

    float acc[4][8][4];
#pragma unroll
    for (int a = 0; a < 4; a++)
#pragma unroll
        for (int b = 0; b < 8; b++)
#pragma unroll
            for (int c = 0; c < 4; c++) acc[a][b][c] = 0.f;

    const uint32_t l15   = (uint32_t)(lane & 15);
    const uint32_t kof16 = (uint32_t)(lane >> 4) * 16u;

    for (int kc = 0; kc < 32; kc++) {
        const int s = kc % GST;
        mbar_wait(mf[s], (kc / GST) & 1);
        const uint32_t Abase = dbase + s * GSTAGE;
        const uint32_t Bbase = Abase + GA_BYTES;
#pragma unroll
        for (int ks = 0; ks < 4; ks++) {
            const uint32_t kb = (uint32_t)ks * 32u + kof16;
            uint32_t a[4][4];
#pragma unroll
            for (int mt = 0; mt < 4; mt++) {
                uint32_t row = (uint32_t)(wm * 64 + mt * 16) + l15;
                ldsm4(a[mt], Abase + swz128(row * 128u + kb));
            }
            uint32_t bf[4][4];
#pragma unroll
            for (int np = 0; np < 4; np++) {
                uint32_t row = (uint32_t)(wn * 64 + np * 16) + l15;
                ldsm4(bf[np], Bbase + swz128(row * 128u + kb));
            }
#pragma unroll
            for (int mt = 0; mt < 4; mt++)
#pragma unroll
                for (int np = 0; np < 4; np++) {
                    mma16816(acc[mt][2 * np],     a[mt], bf[np][0], bf[np][2]);
                    mma16816(acc[mt][2 * np + 1], a[mt], bf[np][1], bf[np][3]);
                }
        }
        mbar_arrive(me[s]);
        if (tid == 0) {
            const int kf = kc + GST;
            if (kf < 32) { mbar_wait(me[s], (kc / GST) & 1); fill(kf); }
        }
    }

    // epilogue: regs -> global (row-major C)
    const int g = lane >> 2, t4 = lane & 3;
    OutT* C = (OutT*)ga.C[z];
    const float alpha = ga.alpha[z];
#pragma unroll
    for (int mt = 0; mt < 4; mt++) {
#pragma unroll
        for (int nt = 0; nt < 8; nt++) {
            int row = bm + wm * 64 + mt * 16 + g;
            int cl  = wn * 64 + nt * 8 + 2 * t4;
            int col = bn + cl;
            float b0 = sBias[cl], b1 = sBias[cl + 1];
            float v0 = (acc[mt][nt][0] + b0) * alpha;
            float v1 = (acc[mt][nt][1] + b1) * alpha;
            float v2 = (acc[mt][nt][2] + b0) * alpha;
            float v3 = (acc[mt][nt][3] + b1) * alpha;
            if constexpr (sizeof(OutT) == 2) {
                *reinterpret_cast<__half2*>(&C[(size_t)row * HID + col])       = __floats2half2_rn(v0, v1);
                *reinterpret_cast<__half2*>(&C[(size_t)(row + 8) * HID + col]) = __floats2half2_rn(v2, v3);
            } else {
                *reinterpret_cast<float2*>(&C[(size_t)row * HID + col])       = make_float2(v0, v1);
                *reinterpret_cast<float2*>(&C[(size_t)(row + 8) * HID + col]) = make_float2(v2, v3);
            }
        }
    }
}

// ---- attention (complement of sliding causal band): keep j>i or j<=i-WIN ---
#define APITCH 136
#define ATT_SMEM (5 * 128 * APITCH * 2)

__global__ __launch_bounds__(256, 1) void attn_kernel(const __half* __restrict__ Q,
                                                      const __half* __restrict__ K,
                                                      const __half* __restrict__ V,
                                                      char* __restrict__ Oswz) {
    extern __shared__ __half sm[];
    __half* sQ = sm;
    __half* sK = sm + 128 * APITCH;
    __half* sV = sK + 2 * 128 * APITCH;

    const int tid = threadIdx.x, warp = tid >> 5, lane = tid & 31;
    const int bh = blockIdx.y, b = bh >> 4, h = bh & 15;
    const int q0 = blockIdx.x * 128;
    const size_t headoff = ((size_t)b * SEQ) * HID + (size_t)h * HDIM;

#pragma unroll
    for (int v = tid; v < 2048; v += 256) {
        int r = v >> 4, c = (v & 15) * 8;
        cpasync16(smem_u32(&sQ[r * APITCH + c]), Q + headoff + (size_t)(q0 + r) * HID + c);
    }
    CP_COMMIT();

    int list[16], nv = 0;
#pragma unroll
    for (int tt = 0; tt < 16; tt++) {
        int k0 = tt << 7;
        bool skip = (k0 >= q0 - 384) && (k0 <= q0 - 128);
        if (!skip) list[nv++] = tt;
    }

    {
        int k0 = list[0] << 7;
#pragma unroll
        for (int v = tid; v < 2048; v += 256) {
            int r = v >> 4, c = (v & 15) * 8;
            size_t go = headoff + (size_t)(k0 + r) * HID + c;
            cpasync16(smem_u32(&sK[r * APITCH + c]), K + go);
            cpasync16(smem_u32(&sV[r * APITCH + c]), V + go);
        }
        CP_COMMIT();
    }

    CP_WAIT1();
    __syncthreads();

    uint32_t qa[8][4];
    const int mbase = warp * 16;
#pragma unroll
    for (int kt = 0; kt < 8; kt++)
        ldsm4(qa[kt], smem_u32(&sQ[(mbase + (lane & 15)) * APITCH + kt * 16 + (lane >> 4) * 8]));

    float accO[16][4];
#pragma unroll
    for (int a = 0; a < 16; a++)
#pragma unroll
        for (int c = 0; c < 4; c++) accO[a][c] = 0.f;

    const int g = lane >> 2, t4 = lane & 3;
    const int qi0 = q0 + mbase + g, qi1 = qi0 + 8;
    float m0 = -1e30f, m1 = -1e30f, l0 = 0.f, l1 = 0.f;

    for (int ii = 0; ii < nv; ii++) {
        const int tt = list[ii], k0 = tt << 7, cur = ii & 1;
        CP_WAIT0();
        __syncthreads();
        if (ii + 1 < nv) {
            int kn = list[ii + 1] << 7, nb = cur ^ 1;
#pragma unroll
            for (int v = tid; v < 2048; v += 256) {
                int r = v >> 4, c = (v & 15) * 8;
                size_t go = headoff + (size_t)(kn + r) * HID + c;
                cpasync16(smem_u32(&sK[(nb * 128 + r) * APITCH + c]), K + go);
                cpasync16(smem_u32(&sV[(nb * 128 + r) * APITCH + c]), V + go);
            }
            CP_COMMIT();
        }
        const __half* sKc = sK + cur * 128 * APITCH;
        const __half* sVc = sV + cur * 128 * APITCH;

        float s[16][4];
#pragma unroll
        for (int a = 0; a < 16; a++)
#pragma unroll
            for (int c = 0; c < 4; c++) s[a][c] = 0.f;
#pragma unroll
        for (int kt = 0; kt < 8; kt++) {
#pragma unroll
            for (int np = 0; np < 8; np++) {
                uint32_t r[4];
                ldsm4(r, smem_u32(&sKc[(np * 16 + (lane & 15)) * APITCH + kt * 16 + (lane >> 4) * 8]));
                mma16816(s[2 * np],     qa[kt], r[0], r[2]);
                mma16816(s[2 * np + 1], qa[kt], r[1], r[3]);
            }
        }

        if (k0 == q0) {
#pragma unroll
            for (int nt = 0; nt < 16; nt++) {
                int j = k0 + nt * 8 + 2 * t4;
                if (j     <= qi0) s[nt][0] = -1e30f;
                if (j + 1 <= qi0) s[nt][1] = -1e30f;
                if (j     <= qi1) s[nt][2] = -1e30f;
                if (j + 1 <= qi1) s[nt][3] = -1e30f;
            }
        } else if (k0 == q0 - WIN) {
#pragma unroll
            for (int nt = 0; nt < 16; nt++) {
                int j = k0 + nt * 8 + 2 * t4;
                if (j     > qi0 - WIN) s[nt][0] = -1e30f;
                if (j + 1 > qi0 - WIN) s[nt][1] = -1e30f;
                if (j     > qi1 - WIN) s[nt][2] = -1e30f;
                if (j + 1 > qi1 - WIN) s[nt][3] = -1e30f;
            }
        }

        float rm0 = -1e30f, rm1 = -1e30f;
#pragma unroll
        for (int nt = 0; nt < 16; nt++) {
            rm0 = fmaxf(rm0, fmaxf(s[nt][0], s[nt][1]));
            rm1 = fmaxf(rm1, fmaxf(s[nt][2], s[nt][3]));
        }
        rm0 = fmaxf(rm0, __shfl_xor_sync(0xffffffffu, rm0, 1));
        rm0 = fmaxf(rm0, __shfl_xor_sync(0xffffffffu, rm0, 2));
        rm1 = fmaxf(rm1, __shfl_xor_sync(0xffffffffu, rm1, 1));
        rm1 = fmaxf(rm1, __shfl_xor_sync(0xffffffffu, rm1, 2));

        float nm0 = fmaxf(m0, rm0), nm1 = fmaxf(m1, rm1);
        float nm0s = (nm0 < -1e29f) ? 0.f : nm0;
        float nm1s = (nm1 < -1e29f) ? 0.f : nm1;
        float al0 = __expf(m0 - nm0s), al1 = __expf(m1 - nm1s);
        float rs0 = 0.f, rs1 = 0.f;
#pragma unroll
        for (int nt = 0; nt < 16; nt++) {
            s[nt][0] = __expf(s[nt][0] - nm0s);
            s[nt][1] = __expf(s[nt][1] - nm0s);
            s[nt][2] = __expf(s[nt][2] - nm1s);
            s[nt][3] = __expf(s[nt][3] - nm1s);
            rs0 += s[nt][0] + s[nt][1];
            rs1 += s[nt][2] + s[nt][3];
        }
        rs0 += __shfl_xor_sync(0xffffffffu, rs0, 1);
        rs0 += __shfl_xor_sync(0xffffffffu, rs0, 2);
        rs1 += __shfl_xor_sync(0xffffffffu, rs1, 1);
        rs1 += __shfl_xor_sync(0xffffffffu, rs1, 2);
        l0 = l0 * al0 + rs0;
        l1 = l1 * al1 + rs1;
        m0 = nm0; m1 = nm1;
#pragma unroll
        for (int nt = 0; nt < 16; nt++) {
            accO[nt][0] *= al0; accO[nt][1] *= al0;
            accO[nt][2] *= al1; accO[nt][3] *= al1;
        }

#pragma unroll
        for (int kt = 0; kt < 8; kt++) {
            uint32_t pa[4];
            pa[0] = packh2(s[2 * kt][0],     s[2 * kt][1]);
            pa[1] = packh2(s[2 * kt][2],     s[2 * kt][3]);
            pa[2] = packh2(s[2 * kt + 1][0], s[2 * kt + 1][1]);
            pa[3] = packh2(s[2 * kt + 1][2], s[2 * kt + 1][3]);
#pragma unroll
            for (int dp = 0; dp < 8; dp++) {
                uint32_t r[4];
                ldsm4t(r, smem_u32(&sVc[(kt * 16 + (lane & 15)) * APITCH + dp * 16 + (lane >> 4) * 8]));
                mma16816(accO[2 * dp],     pa, r[0], r[1]);
                mma16816(accO[2 * dp + 1], pa, r[2], r[3]);
            }
        }
    }

    // epilogue -> blocked-SW128 A layout (row = b*SEQ+qi, col = h*HDIM+d)
    const float inv0 = 1.f / l0, inv1 = 1.f / l1;
    const int r0g = b * SEQ + qi0, r1g = b * SEQ + qi1;
    const uint32_t blk0 = (uint32_t)((r0g >> 7) * 32 + h * 2);
    const uint32_t rin0 = (uint32_t)(r0g & 127) * 128u;
    const uint32_t rin1 = (uint32_t)(r1g & 127) * 128u;
#pragma unroll
    for (int nt = 0; nt < 16; nt++) {
        int d = nt * 8 + 2 * t4;
        uint32_t base = (blk0 + (uint32_t)(d >> 6)) * 16384u;
        uint32_t c2 = (uint32_t)(d & 63) * 2u;
        *reinterpret_cast<uint32_t*>(Oswz + base + swz128(rin0 + c2)) =
            packh2(accO[nt][0] * inv0, accO[nt][1] * inv0);
        *reinterpret_cast<uint32_t*>(Oswz + base + swz128(rin1 + c2)) =
            packh2(accO[nt][2] * inv1, accO[nt][3] * inv1);
    }
}

// ---- launcher --------------------------------------------------------------
extern "C" void kernel_launch(void* const* d_in, const int* in_sizes, int n_in,
                              void* d_out, int out_size) {
    (void)in_sizes; (void)n_in; (void)out_size;
    const float* x    = (const float*)d_in[0];
    const float* ln_s = (const float*)d_in[1];
    const float* ln_b = (const float*)d_in[2];
    const float* wq   = (const float*)d_in[3];
    const float* bq   = (const float*)d_in[4];
    const float* wk   = (const float*)d_in[5];
    const float* bk   = (const float*)d_in[6];
    const float* wv   = (const float*)d_in[7];
    const float* bv   = (const float*)d_in[8];
    const float* wo   = (const float*)d_in[9];
    const float* bo   = (const float*)d_in[10];
    float* out = (float*)d_out;

    __half *yswz, *oswz, *qh, *kh, *vh, *wqT, *wkT, *wvT, *woT;
    cudaGetSymbolAddress((void**)&yswz, g_yswz);
    cudaGetSymbolAddress((void**)&oswz, g_oswz);
    cudaGetSymbolAddress((void**)&qh,   g_q);
    cudaGetSymbolAddress((void**)&kh,   g_k);
    cudaGetSymbolAddress((void**)&vh,   g_v);
    cudaGetSymbolAddress((void**)&wqT,  g_wqT);
    cudaGetSymbolAddress((void**)&wkT,  g_wkT);
    cudaGetSymbolAddress((void**)&wvT,  g_wvT);
    cudaGetSymbolAddress((void**)&woT,  g_woT);

    cudaFuncSetAttribute(attn_kernel, cudaFuncAttributeMaxDynamicSharedMemorySize, ATT_SMEM);
    cudaFuncSetAttribute(hgemm_kernel<__half>, cudaFuncAttributeMaxDynamicSharedMemorySize, GEMM_DYN);
    cudaFuncSetAttribute(hgemm_kernel<float>,  cudaFuncAttributeMaxDynamicSharedMemorySize, GEMM_DYN);

    dim3 tg(32, 32);
    wtx_kernel<<<tg, 256>>>(wq, wqT);
    wtx_kernel<<<tg, 256>>>(wk, wkT);
    wtx_kernel<<<tg, 256>>>(wv, wvT);
    wtx_kernel<<<tg, 256>>>(wo, woT);

    ln_kernel<<<MROWS, 256>>>(x, ln_s, ln_b, yswz);

    const float qscale = 0.08838834764831845f;   // 1/sqrt(128)
    GemmArgs qkv;
    qkv.Bw[0] = (const char*)wqT; qkv.Bw[1] = (const char*)wkT; qkv.Bw[2] = (const char*)wvT;
    qkv.bias[0] = bq; qkv.bias[1] = bk; qkv.bias[2] = bv;
    qkv.C[0] = qh;   qkv.C[1] = kh;   qkv.C[2] = vh;
    qkv.alpha[0] = qscale; qkv.alpha[1] = 1.f; qkv.alpha[2] = 1.f;
    hgemm_kernel<__half><<<dim3(HID / 256, MROWS / 128, 3), 256, GEMM_DYN>>>(
        (const char*)yswz, qkv);

    attn_kernel<<<dim3(SEQ / 128, 2 * NHEAD), 256, ATT_SMEM>>>(qh, kh, vh, (char*)oswz);

    GemmArgs op;
    op.Bw[0] = (const char*)woT; op.bias[0] = bo; op.C[0] = out; op.alpha[0] = 1.f;
    op.Bw[1] = op.Bw[0]; op.bias[1] = op.bias[0]; op.C[1] = op.C[0]; op.alpha[1] = 1.f;
    op.Bw[2] = op.Bw[0]; op.bias[2] = op.bias[0]; op.C[2] = op.C[0]; op.alpha[2] = 1.f;
    hgemm_kernel<float><<<dim3(HID / 256, MROWS / 128, 1), 256, GEMM_DYN>>>(
        (const char*)oswz, op);
}